// round 15
// baseline (speedup 1.0000x reference)
#include <cuda_runtime.h>
#include <cuda_bf16.h>
#include <cuda_fp16.h>
#include <cstdint>

#define SCALE_ATT 0.17677669529663689f   // 32^-0.5

// Scratch (device globals: allocation-free rule)
__device__ __align__(16) __half g_q[128*8*196*32];    // [B,H,S,DK] fp16
__device__ __align__(16) __half g_k[128*8*196*32];    // [B,H,S,DK] fp16
__device__ __align__(16) __half g_v[128*8*196*128];   // [B,H,S,DV] fp16
__device__ float g_s1[1536], g_t1[1536];
__device__ float g_s2[512],  g_t2[512];

// Pre-converted fp16 operands
__device__ __align__(16) __half g_xh[25088*512];
__device__ __align__(16) __half g_w1h[512*1536];
__device__ __align__(16) __half g_w2h[1024*512];
__device__ __align__(16) __half g_hh[25088*1024];

// ---------------------------------------------------------------------------
// Helpers (baseline PTX only: ldmatrix sm_75+, mma.sync sm_80+, cp.async sm_80+)
// ---------------------------------------------------------------------------
__device__ __forceinline__ uint32_t smem_u32(const void* p) {
    uint32_t a;
    asm("{ .reg .u64 t; cvta.to.shared.u64 t, %1; cvt.u32.u64 %0, t; }" : "=r"(a) : "l"(p));
    return a;
}
#define LDSM_X4(R, addr)                                                      \
    asm volatile("ldmatrix.sync.aligned.m8n8.x4.shared.b16 {%0,%1,%2,%3}, [%4];" \
        : "=r"((R)[0]), "=r"((R)[1]), "=r"((R)[2]), "=r"((R)[3]) : "r"(addr))
#define LDSM_X4T(R, addr)                                                     \
    asm volatile("ldmatrix.sync.aligned.m8n8.x4.trans.shared.b16 {%0,%1,%2,%3}, [%4];" \
        : "=r"((R)[0]), "=r"((R)[1]), "=r"((R)[2]), "=r"((R)[3]) : "r"(addr))

__device__ __forceinline__ void mma_f16(float* c, const uint32_t* a, const uint32_t* b) {
    asm volatile("mma.sync.aligned.m16n8k16.row.col.f32.f16.f16.f32 "
        "{%0,%1,%2,%3}, {%4,%5,%6,%7}, {%8,%9}, {%0,%1,%2,%3};"
        : "+f"(c[0]), "+f"(c[1]), "+f"(c[2]), "+f"(c[3])
        : "r"(a[0]), "r"(a[1]), "r"(a[2]), "r"(a[3]), "r"(b[0]), "r"(b[1]));
}
__device__ __forceinline__ void cp16(uint32_t dst, const void* src) {
    asm volatile("cp.async.cg.shared.global [%0], [%1], 16;" :: "r"(dst), "l"(src));
}
#define CP_COMMIT() asm volatile("cp.async.commit_group;" ::: "memory")
#define CP_WAIT1()  asm volatile("cp.async.wait_group 1;" ::: "memory")
#define CP_WAIT0()  asm volatile("cp.async.wait_group 0;" ::: "memory")

// fast exp2 via MUFU
__device__ __forceinline__ float fexp2(float x) {
    float r;
    asm("ex2.approx.f32 %0, %1;" : "=f"(r) : "f"(x));
    return r;
}

// ---------------------------------------------------------------------------
// Fused prep + fp32->fp16 conversions (single launch; block-range dispatch)
// blocks [0,12544): x ; [12544,13312): W_qkv ; [13312,13824): W_proj ;
// [13824,13830): BN fold
// ---------------------------------------------------------------------------
#define NB_X   12544      // 25088*512/4/256
#define NB_W1  768        // 512*1536/4/256
#define NB_W2  512        // 1024*512/4/256

__global__ void prep_cvt_kernel(const float* __restrict__ x,
                                const float* __restrict__ W_qkv,
                                const float* __restrict__ W_proj,
                                const float* __restrict__ b_qkv,
                                const float* __restrict__ gamma1, const float* __restrict__ beta1,
                                const float* __restrict__ mean1,  const float* __restrict__ var1,
                                const float* __restrict__ b_proj,
                                const float* __restrict__ gamma2, const float* __restrict__ beta2,
                                const float* __restrict__ mean2,  const float* __restrict__ var2) {
    int b = blockIdx.x, tid = threadIdx.x;
    const float* src;
    __half* dst;
    int i;
    if (b < NB_X) {
        src = x;  dst = g_xh;  i = b * 256 + tid;
    } else if (b < NB_X + NB_W1) {
        src = W_qkv;  dst = g_w1h;  i = (b - NB_X) * 256 + tid;
    } else if (b < NB_X + NB_W1 + NB_W2) {
        src = W_proj; dst = g_w2h;  i = (b - NB_X - NB_W1) * 256 + tid;
    } else {
        i = (b - NB_X - NB_W1 - NB_W2) * 256 + tid;
        if (i < 1536) {
            float s = gamma1[i] * rsqrtf(var1[i] + 1e-3f);
            g_s1[i] = s;
            g_t1[i] = (b_qkv[i] - mean1[i]) * s + beta1[i];
        }
        if (i < 512) {
            float s = gamma2[i] * rsqrtf(var2[i] + 1e-3f);
            g_s2[i] = s;
            g_t2[i] = (b_proj[i] - mean2[i]) * s + beta2[i];
        }
        return;
    }
    float4 v = ((const float4*)src)[i];
    __half2 h0 = __floats2half2_rn(v.x, v.y);
    __half2 h1 = __floats2half2_rn(v.z, v.w);
    ((__half2*)dst)[i*2]   = h0;
    ((__half2*)dst)[i*2+1] = h1;
}

// ---------------------------------------------------------------------------
// HMMA GEMM: single-pass fp16, CTA 128x128, Kc=64, 256 thr, 2 CTAs/SM.
// Stage (32768 B): A[128][64]h @0 (128B rows, chunk swizzle c^(r&7)),
//                  B[64][128]h @16384 (256B rows, nch^(k&7)).
// 3-stage cp.async pipeline; fewer barriers than Kc=32.
// MODE 0: x @ W_qkv -> BN fold -> scatter fp16 q/k/v.  MODE 1: hidden @ W_proj -> out
// ---------------------------------------------------------------------------
#define STG 32768

template<int KDIM, int NTOT, int MODE>
__global__ __launch_bounds__(256, 2) void hmma_gemm(float* __restrict__ out) {
    extern __shared__ char smem[];
    uint32_t sb = smem_u32(smem);
    int tid = threadIdx.x, wid = tid >> 5, l = tid & 31;
    int n0 = blockIdx.x * 128, m0 = blockIdx.y * 128;
    int wm = wid & 1, wn = wid >> 1;

    const __half* Ag = (MODE == 0) ? g_xh  : g_hh;
    const __half* Bg = (MODE == 0) ? g_w1h : g_w2h;

    float acc[4][4][4];
    #pragma unroll
    for (int a = 0; a < 4; a++)
        #pragma unroll
        for (int b = 0; b < 4; b++)
            #pragma unroll
            for (int c = 0; c < 4; c++) acc[a][b][c] = 0.f;

    int a_r = tid >> 1;              // A row (2 threads per 64-half row)
    int a_c0 = (tid & 1) * 4;        // 4 chunks of 16B each

    auto issue = [&](int kc) {
        uint32_t stg = sb + (kc % 3) * STG;
        const __half* ap = Ag + (size_t)(m0 + a_r) * KDIM + kc * 64;
        #pragma unroll
        for (int i = 0; i < 4; i++) {
            int c = a_c0 + i;
            uint32_t dst = stg + a_r * 128 + ((uint32_t)(c ^ (a_r & 7)) << 4);
            cp16(dst, ap + c * 8);
        }
        #pragma unroll
        for (int i = 0; i < 4; i++) {
            int q = tid * 4 + i;
            int k = q >> 4, nch = q & 15;
            uint32_t dst = stg + 16384 + k * 256 + ((uint32_t)(nch ^ (k & 7)) << 4);
            cp16(dst, Bg + (size_t)(kc * 64 + k) * NTOT + n0 + nch * 8);
        }
    };

    auto compute = [&](int s) {
        uint32_t base = sb + s * STG;
        #pragma unroll
        for (int ks = 0; ks < 64; ks += 16) {
            uint32_t ah[16], bh[8];
            int c = (ks >> 3) + (l >> 4);
            #pragma unroll
            for (int mt = 0; mt < 4; mt++) {
                int r = wm * 64 + mt * 16 + (l & 15);
                uint32_t ad = base + r * 128 + ((uint32_t)(c ^ (r & 7)) << 4);
                LDSM_X4(&ah[mt*4], ad);
            }
            int bk = ks + (l & 7) + (((l >> 3) & 1) << 3);
            #pragma unroll
            for (int hf = 0; hf < 2; hf++) {
                int nch = wn * 4 + hf * 2 + (l >> 4);
                uint32_t bd = base + 16384 + bk * 256 + ((uint32_t)(nch ^ (bk & 7)) << 4);
                LDSM_X4T(&bh[hf*4], bd);
            }
            #pragma unroll
            for (int mt = 0; mt < 4; mt++)
                #pragma unroll
                for (int nt = 0; nt < 4; nt++)
                    mma_f16(acc[mt][nt], &ah[mt*4], &bh[nt*2]);
        }
    };

    const int NC = KDIM / 64;
    issue(0);
    CP_COMMIT();
    issue(1);
    CP_COMMIT();
    for (int kc = 0; kc < NC; kc++) {
        if (kc < NC - 1) CP_WAIT1(); else CP_WAIT0();
        __syncthreads();
        if (kc + 2 < NC) issue(kc + 2);
        CP_COMMIT();
        compute(kc % 3);
    }

    #pragma unroll
    for (int mt = 0; mt < 4; mt++) {
        int mrow0 = m0 + wm * 64 + mt * 16 + (l >> 2);
        #pragma unroll
        for (int rr = 0; rr < 2; rr++) {
            int m = mrow0 + rr * 8;
            if (MODE == 0) {
                int bb = m / 196;
                int s  = m - bb * 196;
                #pragma unroll
                for (int nt = 0; nt < 4; nt++) {
                    int j = n0 + wn * 32 + nt * 8 + 2 * (l & 3);  // even
                    float v0 = fmaf(acc[mt][nt][rr*2 + 0], g_s1[j],     g_t1[j]);
                    float v1 = fmaf(acc[mt][nt][rr*2 + 1], g_s1[j + 1], g_t1[j + 1]);
                    __half2 p = __floats2half2_rn(v0, v1);
                    int h = j / 192;
                    int r = j - h * 192;            // even; pair stays in segment
                    size_t bhs = (size_t)(bb * 8 + h) * 196 + s;
                    if (r < 32)       *(__half2*)&g_q[bhs * 32 + r] = p;
                    else if (r < 64)  *(__half2*)&g_k[bhs * 32 + (r - 32)] = p;
                    else              *(__half2*)&g_v[bhs * 128 + (r - 64)] = p;
                }
            } else {
                #pragma unroll
                for (int nt = 0; nt < 4; nt++) {
                    int j = n0 + wn * 32 + nt * 8 + 2 * (l & 3);
                    float2 o;
                    o.x = fmaf(acc[mt][nt][rr*2 + 0], g_s2[j],     g_t2[j]);
                    o.y = fmaf(acc[mt][nt][rr*2 + 1], g_s2[j + 1], g_t2[j + 1]);
                    *(float2*)&out[(size_t)m * 512 + j] = o;
                }
            }
        }
    }
}

// ---------------------------------------------------------------------------
// Single-pass fp16 attention (unchanged from R13 passing version)
// ---------------------------------------------------------------------------
#define AQ   0
#define AK   13312
#define AV0  26624
#define ASTG 79872
#define ATTN_SMEM 120832

__global__ __launch_bounds__(256, 1) void attn_kernel() {
    extern __shared__ char smem[];
    uint32_t sb = smem_u32(smem);
    int tid = threadIdx.x, w = tid >> 5, l = tid & 31;
    int bh = blockIdx.x;
    int bb = bh >> 3, hh = bh & 7;
    const __half* qg = g_q + (size_t)bh * 196 * 32;
    const __half* kg = g_k + (size_t)bh * 196 * 32;
    const __half* vg = g_v + (size_t)bh * 196 * 128;

    // ---- stage Q,K (fp16, 64B rows, chunk swizzle c^((r>>1)&3)) ----
    uint4 z4 = make_uint4(0u, 0u, 0u, 0u);
    for (int r = tid; r < 208; r += 256) {
        uint4 qv[4] = {z4, z4, z4, z4}, kv[4] = {z4, z4, z4, z4};
        if (r < 196) {
            const uint4* qp = (const uint4*)(qg + r * 32);
            const uint4* kp = (const uint4*)(kg + r * 32);
            #pragma unroll
            for (int c = 0; c < 4; c++) { qv[c] = qp[c]; kv[c] = kp[c]; }
        }
        #pragma unroll
        for (int c = 0; c < 4; c++) {
            uint32_t off = r * 64 + ((uint32_t)(c ^ ((r >> 1) & 3)) << 4);
            *(uint4*)(smem + AQ + off) = qv[c];
            *(uint4*)(smem + AK + off) = kv[c];
        }
    }
    // ---- stage V (fp16, 256B rows, chunk swizzle c^(r&7)) ----
    for (int i = tid; i < 832; i += 256) {
        int r = i >> 2, q4 = i & 3;
        uint4 vv[4] = {z4, z4, z4, z4};
        if (r < 196) {
            const uint4* vp = (const uint4*)(vg + r * 128 + q4 * 32);
            #pragma unroll
            for (int c = 0; c < 4; c++) vv[c] = vp[c];
        }
        #pragma unroll
        for (int c = 0; c < 4; c++) {
            int ch = q4 * 4 + c;
            uint32_t off = r * 256 + ((uint32_t)(ch ^ (r & 7)) << 4);
            *(uint4*)(smem + AV0 + off) = vv[c];
        }
    }
    __syncthreads();

    float* stg = (float*)(smem + ASTG + w * 5120);
    const float CEXP = SCALE_ATT * 1.44269504f;

    for (int mi = 0; mi < 2; mi++) {
        int mt = w + mi * 8;
        if (mt > 12) continue;

        // ---- scores: single-pass fp16 ----
        float sc[26][4];
        #pragma unroll
        for (int t = 0; t < 26; t++)
            #pragma unroll
            for (int j = 0; j < 4; j++) sc[t][j] = 0.f;

        #pragma unroll
        for (int ks = 0; ks < 2; ks++) {
            uint32_t qh[4];
            int qr = mt*16 + (l & 15);
            int qc = ks*2 + (l >> 4);
            LDSM_X4(qh, sb + AQ + qr*64 + ((uint32_t)(qc ^ ((qr>>1)&3)) << 4));
            #pragma unroll
            for (int ng = 0; ng < 13; ng++) {
                uint32_t kh[4];
                int kr = ng*16 + (l & 15);
                LDSM_X4(kh, sb + AK + kr*64 + ((uint32_t)(qc ^ ((kr>>1)&3)) << 4));
                uint32_t b0[2] = {kh[0], kh[2]}, b1[2] = {kh[1], kh[3]};
                mma_f16(sc[2*ng],   qh, b0);
                mma_f16(sc[2*ng+1], qh, b1);
            }
        }

        // ---- mask key cols >= 196 ----
        if ((l & 3) >= 2) {
            sc[24][0] = sc[24][1] = sc[24][2] = sc[24][3] = -1e30f;
        }
        sc[25][0] = sc[25][1] = sc[25][2] = sc[25][3] = -1e30f;

        // ---- softmax without max-shift (scores O(1)) ----
        float smA = 0.f, smB = 0.f;
        #pragma unroll
        for (int t = 0; t < 26; t++) {
            sc[t][0] = fexp2(CEXP * sc[t][0]);
            sc[t][1] = fexp2(CEXP * sc[t][1]);
            sc[t][2] = fexp2(CEXP * sc[t][2]);
            sc[t][3] = fexp2(CEXP * sc[t][3]);
            smA += sc[t][0] + sc[t][1];
            smB += sc[t][2] + sc[t][3];
        }
        #pragma unroll
        for (int o = 1; o <= 2; o <<= 1) {
            smA += __shfl_xor_sync(0xffffffffu, smA, o);
            smB += __shfl_xor_sync(0xffffffffu, smB, o);
        }
        float ivA = 1.0f / smA, ivB = 1.0f / smB;

        // ---- repack P as fp16 A-frags (in place) ----
        #pragma unroll
        for (int t = 0; t < 26; t++) {
            __half2 hA = __floats2half2_rn(sc[t][0] * ivA, sc[t][1] * ivA);
            __half2 hB = __floats2half2_rn(sc[t][2] * ivB, sc[t][3] * ivB);
            sc[t][0] = *(float*)&hA;
            sc[t][1] = *(float*)&hB;
        }

        // ---- AV: single-pass fp16 over 13 k-steps, 16 d-ntiles ----
        float av[16][4];
        #pragma unroll
        for (int t = 0; t < 16; t++)
            #pragma unroll
            for (int j = 0; j < 4; j++) av[t][j] = 0.f;

        #pragma unroll 1
        for (int kt = 0; kt < 13; kt++) {
            uint32_t aP[4] = { *(uint32_t*)&sc[2*kt][0], *(uint32_t*)&sc[2*kt][1],
                               *(uint32_t*)&sc[2*kt+1][0], *(uint32_t*)&sc[2*kt+1][1] };
            int bk = kt*16 + (l & 7) + (((l >> 3) & 1) << 3);
            #pragma unroll
            for (int dg = 0; dg < 8; dg++) {
                uint32_t vh[4];
                int nch = dg*2 + (l >> 4);
                uint32_t bd = sb + AV0 + bk*256 + ((uint32_t)(nch ^ (bk & 7)) << 4);
                LDSM_X4T(vh, bd);
                mma_f16(av[2*dg],   aP, &vh[0]);
                mma_f16(av[2*dg+1], aP, &vh[2]);
            }
        }

        // ---- hard_swish + transposed store (fp16 hidden) via staging ----
        int s0 = mt * 16;
        int nv = 196 - s0;
        if (nv > 16) nv = 16;
        int rA = l >> 2;
        size_t gbase = (size_t)bb * 200704 + (size_t)hh * 25088;

        #pragma unroll 1
        for (int h2 = 0; h2 < 2; h2++) {
            __syncwarp();
            #pragma unroll
            for (int nt = 8*h2; nt < 8*h2 + 8; nt++) {
                int dl0 = 2*(l & 3) + 8*(nt - 8*h2);
                float x0 = av[nt][0], x1 = av[nt][1], x2 = av[nt][2], x3 = av[nt][3];
                x0 = x0 * __saturatef((x0 + 3.f) * (1.f/6.f));
                x1 = x1 * __saturatef((x1 + 3.f) * (1.f/6.f));
                x2 = x2 * __saturatef((x2 + 3.f) * (1.f/6.f));
                x3 = x3 * __saturatef((x3 + 3.f) * (1.f/6.f));
                stg[dl0*20 + rA]       = x0;
                stg[(dl0+1)*20 + rA]   = x1;
                stg[dl0*20 + rA + 8]   = x2;
                stg[(dl0+1)*20 + rA + 8] = x3;
            }
            __syncwarp();
            #pragma unroll
            for (int rr = 0; rr < 2; rr++) {
                int row = rr*32 + l;
                int d = h2*64 + row;
                float4 f0 = *(float4*)(stg + row*20);
                float4 f1 = *(float4*)(stg + row*20 + 4);
                float4 f2 = *(float4*)(stg + row*20 + 8);
                float4 f3 = *(float4*)(stg + row*20 + 12);
                uint32_t ph[8];
                float fv[16] = {f0.x,f0.y,f0.z,f0.w, f1.x,f1.y,f1.z,f1.w,
                                f2.x,f2.y,f2.z,f2.w, f3.x,f3.y,f3.z,f3.w};
                #pragma unroll
                for (int i = 0; i < 8; i++) {
                    __half2 hv2 = __floats2half2_rn(fv[2*i], fv[2*i+1]);
                    ph[i] = *(uint32_t*)&hv2;
                }
                size_t gidx = gbase + (size_t)d * 196 + s0;
                if (nv == 16) {
                    #pragma unroll
                    for (int i = 0; i < 4; i++)
                        *(uint2*)(g_hh + gidx + i*4) = make_uint2(ph[2*i], ph[2*i+1]);
                } else {
                    *(uint2*)(g_hh + gidx) = make_uint2(ph[0], ph[1]);
                }
            }
        }
    }
}

// ---------------------------------------------------------------------------
extern "C" void kernel_launch(void* const* d_in, const int* in_sizes, int n_in,
                              void* d_out, int out_size) {
    const float* x      = (const float*)d_in[0];
    const float* W_qkv  = (const float*)d_in[1];
    const float* b_qkv  = (const float*)d_in[2];
    const float* gamma1 = (const float*)d_in[3];
    const float* beta1  = (const float*)d_in[4];
    const float* mean1  = (const float*)d_in[5];
    const float* var1   = (const float*)d_in[6];
    const float* W_proj = (const float*)d_in[7];
    const float* b_proj = (const float*)d_in[8];
    const float* gamma2 = (const float*)d_in[9];
    const float* beta2  = (const float*)d_in[10];
    const float* mean2  = (const float*)d_in[11];
    const float* var2   = (const float*)d_in[12];
    float* out = (float*)d_out;

    // Fused prep + conversions (single launch)
    prep_cvt_kernel<<<NB_X + NB_W1 + NB_W2 + 6, 256>>>(
        x, W_qkv, W_proj,
        b_qkv, gamma1, beta1, mean1, var1,
        b_proj, gamma2, beta2, mean2, var2);

    cudaFuncSetAttribute(hmma_gemm<512, 1536, 0>,
                         cudaFuncAttributeMaxDynamicSharedMemorySize, 3 * STG);
    cudaFuncSetAttribute(hmma_gemm<1024, 512, 1>,
                         cudaFuncAttributeMaxDynamicSharedMemorySize, 3 * STG);
    cudaFuncSetAttribute(attn_kernel,
                         cudaFuncAttributeMaxDynamicSharedMemorySize, ATTN_SMEM);

    // GEMM1: [25088,512] @ [512,1536] -> fp16 q/k/v
    dim3 g1(12, 196);
    hmma_gemm<512, 1536, 0><<<g1, 256, 3 * STG>>>(nullptr);

    // Attention (single-pass fp16 HMMA)
    attn_kernel<<<1024, 256, ATTN_SMEM>>>();

    // GEMM2: [25088,1024] @ [1024,512] -> out
    dim3 g2(4, 196);
    hmma_gemm<1024, 512, 1><<<g2, 256, 3 * STG>>>(out);
}